// round 5
// baseline (speedup 1.0000x reference)
#include <cuda_runtime.h>

// QCNN_58025008169535: 4-qubit quantum circuit sim per 2x2 image patch.
// x: [32,128,128,3] f32, w: [4,4,3] f32 -> out: [32, 127*127, 4] f32.
//
// Algebraic structure exploited:
//  - encoding Rz is global phase -> dropped (channel 0 unused)
//  - variational Rx*Ry*Rz fused into one 2x2 complex gate per (layer,qubit),
//    precomputed once (w is shared across all 516K circuits)
//  - layer-0 gates act on a product state -> applied to per-qubit 2-vectors
//    before the outer product
//  - 3 CZs/layer fused into one sign mask; final layer's CZs dropped, and
//    final layer's trailing Rz dropped (diagonal phases invisible to |psi|^2)
//  - <Z_q> via Walsh-style sign tree over probabilities
//  - 2D grid (patch, image): no div-by-16129 in the kernel

#define NQ 4
#define NL 4

constexpr int BATCH = 32;
constexpr int Hh = 128, Ww = 128, Cc = 3;
constexpr int PH = 127, PW = 127;
constexpr int PP = PH * PW;           // 16129 patches per image

// Fused variational gates: U[h][q] = Rz(w2)*Ry(w1)*Rx(w0) (last layer: Ry*Rx),
// 8 floats each (re/im of U00,U01,U10,U11).
__device__ float gU[NL * NQ * 8];

__global__ __launch_bounds__(32)
void precompute_gates(const float* __restrict__ w) {
    int t = threadIdx.x;
    if (t >= NL * NQ) return;
    int layer = t / NQ;
    float a = w[t * 3 + 0], b = w[t * 3 + 1], g = w[t * 3 + 2];
    float ca, sa, cb, sb, cg, sg;
    sincosf(0.5f * a, &sa, &ca);
    sincosf(0.5f * b, &sb, &cb);
    // Final layer: Rz(g) is diagonal phase, invisible to |psi|^2 -> identity.
    if (layer == NL - 1) { cg = 1.0f; sg = 0.0f; }
    else                 { sincosf(0.5f * g, &sg, &cg); }
    // M = Ry(b) * Rx(a)
    float M00r =  cb * ca, M00i =  sb * sa;
    float M01r = -sb * ca, M01i = -cb * sa;
    float M10r =  sb * ca, M10i = -cb * sa;
    float M11r =  cb * ca, M11i = -sb * sa;
    // U = Rz(g) * M : row0 *= (cg - i sg), row1 *= (cg + i sg)
    float* o = &gU[t * 8];
    o[0] = cg * M00r + sg * M00i;  o[1] = cg * M00i - sg * M00r;
    o[2] = cg * M01r + sg * M01i;  o[3] = cg * M01i - sg * M01r;
    o[4] = cg * M10r - sg * M10i;  o[5] = cg * M10i + sg * M10r;
    o[6] = cg * M11r - sg * M11i;  o[7] = cg * M11i + sg * M11r;
}

__global__ __launch_bounds__(256)
void qcnn_kernel(const float* __restrict__ x, float* __restrict__ out) {
    __shared__ float sU[NL * NQ * 8];
    if (threadIdx.x < NL * NQ * 8) sU[threadIdx.x] = gU[threadIdx.x];
    __syncthreads();

    int p = blockIdx.x * blockDim.x + threadIdx.x;  // patch index within image
    if (p >= PP) return;
    int b = blockIdx.y;                              // image index

    int r = p / PW;
    int c = p - r * PW;
    const float* px = x + ((size_t)(b * Hh + r) * Ww + c) * Cc;

    const float PI = 3.14159265358979f;

    // Per-qubit initial vectors (encoding with global phase dropped):
    //   v = (cos th, e^{i ph} sin th), th = pi*c1/2, ph = pi*c2
    // then layer-0 fused gate applied directly to the 2-vector.
    float vr[NQ][2], vi[NQ][2];
#pragma unroll
    for (int n = 0; n < NQ; n++) {
        const float* pp = px + (((n >> 1) * Ww) + (n & 1)) * Cc;
        float c1 = pp[1], c2 = pp[2];
        float st, ct, sp, cp;
        __sincosf(0.5f * PI * c1, &st, &ct);
        __sincosf(PI * c2, &sp, &cp);
        float v0r = ct,      v0i = 0.0f;
        float v1r = st * cp, v1i = st * sp;

        const float* u = &sU[(0 * NQ + n) * 8];
        float u00r = u[0], u00i = u[1], u01r = u[2], u01i = u[3];
        float u10r = u[4], u10i = u[5], u11r = u[6], u11i = u[7];
        vr[n][0] = u00r * v0r - u00i * v0i + u01r * v1r - u01i * v1i;
        vi[n][0] = u00r * v0i + u00i * v0r + u01r * v1i + u01i * v1r;
        vr[n][1] = u10r * v0r - u10i * v0i + u11r * v1r - u11i * v1i;
        vi[n][1] = u10r * v0i + u10i * v0r + u11r * v1i + u11i * v1r;
    }

    // Build 16-amp state via outer products. idx bit3=q0 .. bit0=q3.
    float ar[4], ai[4], brv[4], biv[4];
#pragma unroll
    for (int i = 0; i < 4; i++) {
        int b0 = i >> 1, b1 = i & 1;
        ar[i]  = vr[0][b0] * vr[1][b1] - vi[0][b0] * vi[1][b1];
        ai[i]  = vr[0][b0] * vi[1][b1] + vi[0][b0] * vr[1][b1];
        brv[i] = vr[2][b0] * vr[3][b1] - vi[2][b0] * vi[3][b1];
        biv[i] = vr[2][b0] * vi[3][b1] + vi[2][b0] * vr[3][b1];
    }
    float re[16], im[16];
#pragma unroll
    for (int i = 0; i < 16; i++) {
        int hi = i >> 2, lo = i & 3;
        re[i] = ar[hi] * brv[lo] - ai[hi] * biv[lo];
        im[i] = ar[hi] * biv[lo] + ai[hi] * brv[lo];
    }

    // Layer-0 CZ mask (gates already applied above), then layers 1..NL-1.
    // CZ(0,1),CZ(2,3),CZ(1,2): sign = (-1)^(b0b1 ^ b2b3 ^ b1b2)
#pragma unroll
    for (int i = 0; i < 16; i++) {
        int b0 = (i >> 3) & 1, b1 = (i >> 2) & 1, b2 = (i >> 1) & 1, b3 = i & 1;
        if ((b0 & b1) ^ (b2 & b3) ^ (b1 & b2)) { re[i] = -re[i]; im[i] = -im[i]; }
    }

#pragma unroll
    for (int h = 1; h < NL; h++) {
#pragma unroll
        for (int q = 0; q < NQ; q++) {
            const float* u = &sU[(h * NQ + q) * 8];
            float u00r = u[0], u00i = u[1], u01r = u[2], u01i = u[3];
            float u10r = u[4], u10i = u[5], u11r = u[6], u11i = u[7];
            int s = 8 >> q;  // stride of qubit q
#pragma unroll
            for (int i = 0; i < 16; i++) {
                if (i & s) continue;
                int j = i | s;
                float xr = re[i], xi = im[i], yr = re[j], yi = im[j];
                re[i] = u00r * xr - u00i * xi + u01r * yr - u01i * yi;
                im[i] = u00r * xi + u00i * xr + u01r * yi + u01i * yr;
                re[j] = u10r * xr - u10i * xi + u11r * yr - u11i * yi;
                im[j] = u10r * xi + u10i * xr + u11r * yi + u11i * yr;
            }
        }
        if (h < NL - 1) {  // final layer's CZs are invisible to |psi|^2
#pragma unroll
            for (int i = 0; i < 16; i++) {
                int b0 = (i >> 3) & 1, b1 = (i >> 2) & 1, b2 = (i >> 1) & 1, b3 = i & 1;
                if ((b0 & b1) ^ (b2 & b3) ^ (b1 & b2)) { re[i] = -re[i]; im[i] = -im[i]; }
            }
        }
    }

    // Probabilities, then <Z_q> via a sign tree (36 adds vs 64 naive).
    float pr[16];
#pragma unroll
    for (int i = 0; i < 16; i++) pr[i] = re[i] * re[i] + im[i] * im[i];

    float s8[8], z3 = 0.f;
#pragma unroll
    for (int k = 0; k < 8; k++) {
        s8[k] = pr[2 * k] + pr[2 * k + 1];
        z3 += pr[2 * k] - pr[2 * k + 1];
    }
    float s4[4], z2 = 0.f;
#pragma unroll
    for (int k = 0; k < 4; k++) {
        s4[k] = s8[2 * k] + s8[2 * k + 1];
        z2 += s8[2 * k] - s8[2 * k + 1];
    }
    float z1 = (s4[0] - s4[1]) + (s4[2] - s4[3]);
    float z0 = (s4[0] + s4[1]) - (s4[2] + s4[3]);

    float4 o;
    o.x = z0; o.y = z1; o.z = z2; o.w = z3;
    reinterpret_cast<float4*>(out)[(size_t)b * PP + p] = o;
}

extern "C" void kernel_launch(void* const* d_in, const int* in_sizes, int n_in,
                              void* d_out, int out_size) {
    // Identify x (1.5M elems) vs w (48 elems) defensively by size.
    const float* x = (const float*)d_in[0];
    const float* w = (const float*)d_in[1];
    if (n_in >= 2 && in_sizes[0] < in_sizes[1]) {
        x = (const float*)d_in[1];
        w = (const float*)d_in[0];
    }
    precompute_gates<<<1, 32>>>(w);
    dim3 grid((PP + 255) / 256, BATCH);
    qcnn_kernel<<<grid, 256>>>(x, (float*)d_out);
}